// round 8
// baseline (speedup 1.0000x reference)
#include <cuda_runtime.h>

#define NN 50000
#define EE 800000
#define FF 16
#define CAP 64

// ---------------- device scratch (no allocations allowed) ----------------
__device__ int   g_deg[NN];
__device__ int2  g_bucket[NN * CAP];   // per-dst list of (edge_id, src)
__device__ float g_x[4 * NN * FF];

// ---------------- bucket build ----------------
// 4 edges per thread, single pass: atomic slot grab + direct bucket store
__global__ void k_bucket(const int* __restrict__ ei) {
    int t = blockIdx.x * blockDim.x + threadIdx.x;
    if (t * 4 >= EE) return;
    int4 d4 = reinterpret_cast<const int4*>(ei + EE)[t];
    int4 s4 = reinterpret_cast<const int4*>(ei)[t];
    int e0 = t * 4;
    int p0 = atomicAdd(&g_deg[d4.x], 1);
    int p1 = atomicAdd(&g_deg[d4.y], 1);
    int p2 = atomicAdd(&g_deg[d4.z], 1);
    int p3 = atomicAdd(&g_deg[d4.w], 1);
    if (p0 < CAP) g_bucket[d4.x * CAP + p0] = make_int2(e0 + 0, s4.x);
    if (p1 < CAP) g_bucket[d4.y * CAP + p1] = make_int2(e0 + 1, s4.y);
    if (p2 < CAP) g_bucket[d4.z * CAP + p2] = make_int2(e0 + 2, s4.z);
    if (p3 < CAP) g_bucket[d4.w * CAP + p3] = make_int2(e0 + 3, s4.w);
}

// ---------------- per-node softmax aggregation: one warp per node ----------------
// lane l: edge-parity p=l>>4, component c=(l>>2)&3, quad fq=l&3 (features 4fq..4fq+3).
// Record loads are software-pipelined one iteration ahead (CAP bound makes the
// prefetch always in-bounds). Parity partial sums combined by shfl.
// agg = sum(m*exp(beta*m)) / sum(exp(beta*m))  (shift-free softmax, exact ratio)
__global__ void k_node(const float* __restrict__ q, const float* __restrict__ ea,
                       const float* __restrict__ beta) {
    int w = (blockIdx.x * blockDim.x + threadIdx.x) >> 5;
    if (w >= NN) return;
    int lane = threadIdx.x & 31;
    int p  = lane >> 4;
    int c  = (lane >> 2) & 3;
    int fq = lane & 3;

    const int4* rec4 = reinterpret_cast<const int4*>(g_bucket + w * CAP);  // 2 records per int4

    // prefetch first 8 records immediately (always in-bounds: 32 int4 per row)
    int4 rA0 = rec4[0], rA1 = rec4[1], rA2 = rec4[2], rA3 = rec4[3];

    int cnt = g_deg[w];
    if (cnt > CAP) cnt = CAP;
    float bta = __ldg(beta);

    const float4* qc = reinterpret_cast<const float4*>(q)  + (size_t)c * NN * 4 + fq;
    const float4* ac = reinterpret_cast<const float4*>(ea) + (size_t)c * EE * 4 + fq;

    float4 sez = make_float4(0.f, 0.f, 0.f, 0.f);
    float4 smz = make_float4(0.f, 0.f, 0.f, 0.f);

#define ACC4(aa, bb)                                                       \
    {                                                                      \
        float m0 = aa.x + bb.x, m1 = aa.y + bb.y;                          \
        float m2 = aa.z + bb.z, m3 = aa.w + bb.w;                          \
        float z0 = __expf(m0 * bta), z1 = __expf(m1 * bta);                \
        float z2 = __expf(m2 * bta), z3 = __expf(m3 * bta);                \
        sez.x += z0; smz.x = fmaf(m0, z0, smz.x);                          \
        sez.y += z1; smz.y = fmaf(m1, z1, smz.y);                          \
        sez.z += z2; smz.z = fmaf(m2, z2, smz.z);                          \
        sez.w += z3; smz.w = fmaf(m3, z3, smz.w);                          \
    }

    int base = 0;
    // 8 edges per iteration; records for the NEXT iteration prefetched before
    // this iteration's gathers are consumed.
    for (; base + 8 <= cnt; base += 8) {
        int qi = (base >> 1) + 4;          // next iteration's records (bounded by CAP row)
        int4 rB0 = rec4[(qi & 31)];
        int4 rB1 = rec4[((qi + 1) & 31)];
        int4 rB2 = rec4[((qi + 2) & 31)];
        int4 rB3 = rec4[((qi + 3) & 31)];

        int e0 = p ? rA0.z : rA0.x, s0 = p ? rA0.w : rA0.y;
        int e1 = p ? rA1.z : rA1.x, s1 = p ? rA1.w : rA1.y;
        int e2 = p ? rA2.z : rA2.x, s2 = p ? rA2.w : rA2.y;
        int e3 = p ? rA3.z : rA3.x, s3 = p ? rA3.w : rA3.y;
        float4 a0 = __ldg(ac + e0 * 4), b0 = __ldg(qc + s0 * 4);
        float4 a1 = __ldg(ac + e1 * 4), b1 = __ldg(qc + s1 * 4);
        float4 a2 = __ldg(ac + e2 * 4), b2 = __ldg(qc + s2 * 4);
        float4 a3 = __ldg(ac + e3 * 4), b3 = __ldg(qc + s3 * 4);
        ACC4(a0, b0) ACC4(a1, b1) ACC4(a2, b2) ACC4(a3, b3)

        rA0 = rB0; rA1 = rB1; rA2 = rB2; rA3 = rB3;
    }
    // 2-edge steps (records are in L2 by now; direct loads)
    for (; base + 2 <= cnt; base += 2) {
        int4 r0 = rec4[base >> 1];
        int e0 = p ? r0.z : r0.x, s0 = p ? r0.w : r0.y;
        float4 a0 = __ldg(ac + e0 * 4), b0 = __ldg(qc + s0 * 4);
        ACC4(a0, b0)
    }
    // odd tail: only parity 0 lanes process it (counted once after reduction)
    if (base < cnt && p == 0) {
        int2 r = g_bucket[w * CAP + base];
        float4 a0 = __ldg(ac + r.x * 4), b0 = __ldg(qc + r.y * 4);
        ACC4(a0, b0)
    }
#undef ACC4

    // combine parity halves (lane ^ 16 holds the same channel's other partial)
    sez.x += __shfl_xor_sync(0xffffffffu, sez.x, 16);
    sez.y += __shfl_xor_sync(0xffffffffu, sez.y, 16);
    sez.z += __shfl_xor_sync(0xffffffffu, sez.z, 16);
    sez.w += __shfl_xor_sync(0xffffffffu, sez.w, 16);
    smz.x += __shfl_xor_sync(0xffffffffu, smz.x, 16);
    smz.y += __shfl_xor_sync(0xffffffffu, smz.y, 16);
    smz.z += __shfl_xor_sync(0xffffffffu, smz.z, 16);
    smz.w += __shfl_xor_sync(0xffffffffu, smz.w, 16);

    if (p == 0) {
        float4 self = __ldg(qc + w * 4);
        float4 o;
        o.x = self.x + ((sez.x > 0.f) ? (smz.x / sez.x) : 0.f);
        o.y = self.y + ((sez.y > 0.f) ? (smz.y / sez.y) : 0.f);
        o.z = self.z + ((sez.z > 0.f) ? (smz.z / sez.z) : 0.f);
        o.w = self.w + ((sez.w > 0.f) ? (smz.w / sez.w) : 0.f);
        reinterpret_cast<float4*>(g_x)[(size_t)c * NN * 4 + w * 4 + fq] = o;
    }
}

// ---------------- quaternion MLP: 4 threads per node (feature quarters) ----------------
// acc[co] = output features qt*4..qt*4+3 of component co
__device__ __forceinline__ void qlin_q(const float* sxb, int i17, int qt,
                                       const float* __restrict__ W,
                                       const float* __restrict__ B,
                                       float4* acc) {
    const int SGN[4][4] = { { 1,  1,  1,  1},
                            { 1, -1,  1, -1},
                            { 1, -1, -1,  1},
                            { 1,  1, -1, -1} };
#pragma unroll
    for (int co = 0; co < 4; ++co)
        acc[co] = reinterpret_cast<const float4*>(B)[co * 4 + qt];

#pragma unroll 4
    for (int fi = 0; fi < 16; ++fi) {
        float a[4];
#pragma unroll
        for (int ci = 0; ci < 4; ++ci) a[ci] = sxb[ci * 2176 + i17 + fi];
#pragma unroll
        for (int cw = 0; cw < 4; ++cw) {
            float4 wv = reinterpret_cast<const float4*>(W + cw * 256 + fi * 16)[qt];
#pragma unroll
            for (int ci = 0; ci < 4; ++ci) {
                const int co = ci ^ cw;
                const float av = (SGN[ci][cw] > 0) ? a[ci] : -a[ci];
                float4* pp = &acc[co];
                pp->x = fmaf(av, wv.x, pp->x); pp->y = fmaf(av, wv.y, pp->y);
                pp->z = fmaf(av, wv.z, pp->z); pp->w = fmaf(av, wv.w, pp->w);
            }
        }
    }
}

__global__ __launch_bounds__(512) void k_mlp(const float* __restrict__ W1, const float* __restrict__ B1,
                                             const float* __restrict__ W2, const float* __restrict__ B2,
                                             float* __restrict__ out) {
    __shared__ __align__(16) float sx[4 * 2176];       // 128 nodes * stride17 * 4 comps
    __shared__ __align__(16) float sw1[1024], sw2[1024];
    __shared__ __align__(16) float sb1[64],  sb2[64];

    const int tid  = threadIdx.x;
    const int node = tid >> 2;        // 0..127 within block
    const int qt   = tid & 3;         // feature quarter
    const int n0   = blockIdx.x * 128;
    int nv = NN - n0; if (nv > 128) nv = 128;
    const int cnt = nv * 16;

    for (int i = tid; i < 1024; i += 512) { sw1[i] = W1[i]; sw2[i] = W2[i]; }
    if (tid < 64) { sb1[tid] = B1[tid]; sb2[tid] = B2[tid]; }

#pragma unroll
    for (int c = 0; c < 4; ++c) {
        const float* src = g_x + (size_t)c * NN * FF + n0 * FF;
        for (int i = tid; i < cnt; i += 512)
            sx[c * 2176 + (i >> 4) * 17 + (i & 15)] = src[i];
    }
    __syncthreads();

    const int i17 = node * 17;
    float4 h[4];

    // layer 1 + relu
    qlin_q(sx, i17, qt, sw1, sb1, h);
#pragma unroll
    for (int k = 0; k < 4; ++k) {
        h[k].x = fmaxf(h[k].x, 0.f); h[k].y = fmaxf(h[k].y, 0.f);
        h[k].z = fmaxf(h[k].z, 0.f); h[k].w = fmaxf(h[k].w, 0.f);
    }
    __syncthreads();
#pragma unroll
    for (int co = 0; co < 4; ++co) {
        float* p = sx + co * 2176 + i17 + qt * 4;
        p[0] = h[co].x; p[1] = h[co].y; p[2] = h[co].z; p[3] = h[co].w;
    }
    __syncthreads();

    // layer 2
    qlin_q(sx, i17, qt, sw2, sb2, h);
    __syncthreads();
#pragma unroll
    for (int co = 0; co < 4; ++co) {
        float* p = sx + co * 2176 + i17 + qt * 4;
        p[0] = h[co].x; p[1] = h[co].y; p[2] = h[co].z; p[3] = h[co].w;
    }
    __syncthreads();

    // coalesced store
#pragma unroll
    for (int c = 0; c < 4; ++c) {
        float* dst = out + (size_t)c * NN * FF + n0 * FF;
        for (int i = tid; i < cnt; i += 512)
            dst[i] = sx[c * 2176 + (i >> 4) * 17 + (i & 15)];
    }
}

// ---------------- launch ----------------
extern "C" void kernel_launch(void* const* d_in, const int* in_sizes, int n_in,
                              void* d_out, int out_size) {
    const float* q    = (const float*)d_in[0];
    const float* ea   = (const float*)d_in[1];
    const int*   ei   = (const int*)d_in[2];
    const float* W1   = (const float*)d_in[3];
    const float* B1   = (const float*)d_in[4];
    const float* W2   = (const float*)d_in[5];
    const float* B2   = (const float*)d_in[6];
    const float* beta = (const float*)d_in[7];
    float* out = (float*)d_out;

    void* degp = nullptr;
    cudaGetSymbolAddress(&degp, g_deg);
    cudaMemsetAsync(degp, 0, NN * sizeof(int));

    k_bucket<<<(EE / 4 + 255) / 256, 256>>>(ei);
    k_node<<<(NN * 32 + 255) / 256, 256>>>(q, ea, beta);
    k_mlp<<<(NN + 127) / 128, 512>>>(W1, B1, W2, B2, out);
}

// round 9
// speedup vs baseline: 1.1319x; 1.1319x over previous
#include <cuda_runtime.h>

#define NN 50000
#define EE 800000
#define FF 16
#define CAP 64

// ---------------- device scratch (no allocations allowed) ----------------
__device__ int   g_deg[NN];
__device__ int2  g_bucket[NN * CAP];   // per-dst list of (edge_id, src)
__device__ float g_x[4 * NN * FF];

// ---------------- bucket build ----------------
// 4 edges per thread, single pass: atomic slot grab + direct bucket store
__global__ void k_bucket(const int* __restrict__ ei) {
    int t = blockIdx.x * blockDim.x + threadIdx.x;
    if (t * 4 >= EE) return;
    int4 d4 = reinterpret_cast<const int4*>(ei + EE)[t];
    int4 s4 = reinterpret_cast<const int4*>(ei)[t];
    int e0 = t * 4;
    int p0 = atomicAdd(&g_deg[d4.x], 1);
    int p1 = atomicAdd(&g_deg[d4.y], 1);
    int p2 = atomicAdd(&g_deg[d4.z], 1);
    int p3 = atomicAdd(&g_deg[d4.w], 1);
    if (p0 < CAP) g_bucket[d4.x * CAP + p0] = make_int2(e0 + 0, s4.x);
    if (p1 < CAP) g_bucket[d4.y * CAP + p1] = make_int2(e0 + 1, s4.y);
    if (p2 < CAP) g_bucket[d4.z * CAP + p2] = make_int2(e0 + 2, s4.z);
    if (p3 < CAP) g_bucket[d4.w * CAP + p3] = make_int2(e0 + 3, s4.w);
}

// ---------------- per-node softmax aggregation: one warp per node ----------------
// lane l: edge-parity p=l>>4, component c=(l>>2)&3, quad fq=l&3 (features 4fq..4fq+3).
// One warp-LDG covers 2 edges x 4 comps x 16B. Parity partial sums combined by shfl.
// agg = sum(m*exp(beta*m)) / sum(exp(beta*m))  (shift-free softmax, exact ratio)
__global__ void k_node(const float* __restrict__ q, const float* __restrict__ ea,
                       const float* __restrict__ beta) {
    int w = (blockIdx.x * blockDim.x + threadIdx.x) >> 5;
    if (w >= NN) return;
    int lane = threadIdx.x & 31;
    int p  = lane >> 4;
    int c  = (lane >> 2) & 3;
    int fq = lane & 3;

    float bta = __ldg(beta);
    int cnt = g_deg[w];
    if (cnt > CAP) cnt = CAP;

    const int4*   rec4 = reinterpret_cast<const int4*>(g_bucket + w * CAP);  // 2 records per int4
    const float4* qc = reinterpret_cast<const float4*>(q)  + (size_t)c * NN * 4 + fq;
    const float4* ac = reinterpret_cast<const float4*>(ea) + (size_t)c * EE * 4 + fq;

    float4 sez = make_float4(0.f, 0.f, 0.f, 0.f);
    float4 smz = make_float4(0.f, 0.f, 0.f, 0.f);

#define ACC4(aa, bb)                                                       \
    {                                                                      \
        float m0 = aa.x + bb.x, m1 = aa.y + bb.y;                          \
        float m2 = aa.z + bb.z, m3 = aa.w + bb.w;                          \
        float z0 = __expf(m0 * bta), z1 = __expf(m1 * bta);                \
        float z2 = __expf(m2 * bta), z3 = __expf(m3 * bta);                \
        sez.x += z0; smz.x = fmaf(m0, z0, smz.x);                          \
        sez.y += z1; smz.y = fmaf(m1, z1, smz.y);                          \
        sez.z += z2; smz.z = fmaf(m2, z2, smz.z);                          \
        sez.w += z3; smz.w = fmaf(m3, z3, smz.w);                          \
    }

    int base = 0;
    // 8 edges per iteration: 4 broadcast int4 record loads + 8 gathers in flight per lane
    for (; base + 8 <= cnt; base += 8) {
        int4 r0 = rec4[(base >> 1) + 0];
        int4 r1 = rec4[(base >> 1) + 1];
        int4 r2 = rec4[(base >> 1) + 2];
        int4 r3 = rec4[(base >> 1) + 3];
        int e0 = p ? r0.z : r0.x, s0 = p ? r0.w : r0.y;
        int e1 = p ? r1.z : r1.x, s1 = p ? r1.w : r1.y;
        int e2 = p ? r2.z : r2.x, s2 = p ? r2.w : r2.y;
        int e3 = p ? r3.z : r3.x, s3 = p ? r3.w : r3.y;
        float4 a0 = __ldg(ac + e0 * 4), b0 = __ldg(qc + s0 * 4);
        float4 a1 = __ldg(ac + e1 * 4), b1 = __ldg(qc + s1 * 4);
        float4 a2 = __ldg(ac + e2 * 4), b2 = __ldg(qc + s2 * 4);
        float4 a3 = __ldg(ac + e3 * 4), b3 = __ldg(qc + s3 * 4);
        ACC4(a0, b0) ACC4(a1, b1) ACC4(a2, b2) ACC4(a3, b3)
    }
    // 2-edge steps
    for (; base + 2 <= cnt; base += 2) {
        int4 r0 = rec4[base >> 1];
        int e0 = p ? r0.z : r0.x, s0 = p ? r0.w : r0.y;
        float4 a0 = __ldg(ac + e0 * 4), b0 = __ldg(qc + s0 * 4);
        ACC4(a0, b0)
    }
    // odd tail: only parity 0 lanes process it (counted once after reduction)
    if (base < cnt && p == 0) {
        int2 r = g_bucket[w * CAP + base];
        float4 a0 = __ldg(ac + r.x * 4), b0 = __ldg(qc + r.y * 4);
        ACC4(a0, b0)
    }
#undef ACC4

    // combine parity halves (lane ^ 16 holds the same channel's other partial)
    sez.x += __shfl_xor_sync(0xffffffffu, sez.x, 16);
    sez.y += __shfl_xor_sync(0xffffffffu, sez.y, 16);
    sez.z += __shfl_xor_sync(0xffffffffu, sez.z, 16);
    sez.w += __shfl_xor_sync(0xffffffffu, sez.w, 16);
    smz.x += __shfl_xor_sync(0xffffffffu, smz.x, 16);
    smz.y += __shfl_xor_sync(0xffffffffu, smz.y, 16);
    smz.z += __shfl_xor_sync(0xffffffffu, smz.z, 16);
    smz.w += __shfl_xor_sync(0xffffffffu, smz.w, 16);

    if (p == 0) {
        float4 self = __ldg(qc + w * 4);
        float4 o;
        o.x = self.x + ((sez.x > 0.f) ? (smz.x / sez.x) : 0.f);
        o.y = self.y + ((sez.y > 0.f) ? (smz.y / sez.y) : 0.f);
        o.z = self.z + ((sez.z > 0.f) ? (smz.z / sez.z) : 0.f);
        o.w = self.w + ((sez.w > 0.f) ? (smz.w / sez.w) : 0.f);
        reinterpret_cast<float4*>(g_x)[(size_t)c * NN * 4 + w * 4 + fq] = o;
    }
}

// ---------------- quaternion MLP: 2 threads per node (feature halves) ----------------
// acc[co*2+u] = output features (half*8 + u*4 .. +4) of component co
__device__ __forceinline__ void qlin_h(const float* sxb, int i17, int half,
                                       const float* __restrict__ W,
                                       const float* __restrict__ B,
                                       float4* acc) {
    const int SGN[4][4] = { { 1,  1,  1,  1},
                            { 1, -1,  1, -1},
                            { 1, -1, -1,  1},
                            { 1,  1, -1, -1} };
#pragma unroll
    for (int co = 0; co < 4; ++co) {
        acc[co * 2 + 0] = reinterpret_cast<const float4*>(B)[co * 4 + half * 2 + 0];
        acc[co * 2 + 1] = reinterpret_cast<const float4*>(B)[co * 4 + half * 2 + 1];
    }

#pragma unroll 4
    for (int fi = 0; fi < 16; ++fi) {
        float a[4];
#pragma unroll
        for (int ci = 0; ci < 4; ++ci) a[ci] = sxb[ci * 2176 + i17 + fi];
#pragma unroll
        for (int cw = 0; cw < 4; ++cw) {
            const float4* wr = reinterpret_cast<const float4*>(W + cw * 256 + fi * 16 + half * 8);
            float4 w0 = wr[0], w1 = wr[1];
#pragma unroll
            for (int ci = 0; ci < 4; ++ci) {
                const int co = ci ^ cw;
                const float av = (SGN[ci][cw] > 0) ? a[ci] : -a[ci];
                float4* p0 = &acc[co * 2 + 0];
                float4* p1 = &acc[co * 2 + 1];
                p0->x = fmaf(av, w0.x, p0->x); p0->y = fmaf(av, w0.y, p0->y);
                p0->z = fmaf(av, w0.z, p0->z); p0->w = fmaf(av, w0.w, p0->w);
                p1->x = fmaf(av, w1.x, p1->x); p1->y = fmaf(av, w1.y, p1->y);
                p1->z = fmaf(av, w1.z, p1->z); p1->w = fmaf(av, w1.w, p1->w);
            }
        }
    }
}

__global__ __launch_bounds__(256) void k_mlp(const float* __restrict__ W1, const float* __restrict__ B1,
                                             const float* __restrict__ W2, const float* __restrict__ B2,
                                             float* __restrict__ out) {
    __shared__ __align__(16) float sx[4 * 2176];       // 128 nodes * stride17 * 4 comps
    __shared__ __align__(16) float sw1[1024], sw2[1024];
    __shared__ __align__(16) float sb1[64],  sb2[64];

    const int tid  = threadIdx.x;
    const int node = tid >> 1;        // 0..127 within block
    const int half = tid & 1;         // feature half
    const int n0   = blockIdx.x * 128;
    int nv = NN - n0; if (nv > 128) nv = 128;
    const int cnt = nv * 16;

    for (int i = tid; i < 1024; i += 256) { sw1[i] = W1[i]; sw2[i] = W2[i]; }
    if (tid < 64) { sb1[tid] = B1[tid]; sb2[tid] = B2[tid]; }

#pragma unroll
    for (int c = 0; c < 4; ++c) {
        const float* src = g_x + (size_t)c * NN * FF + n0 * FF;
        for (int i = tid; i < cnt; i += 256)
            sx[c * 2176 + (i >> 4) * 17 + (i & 15)] = src[i];
    }
    __syncthreads();

    const int i17 = node * 17;
    float4 h[8];

    // layer 1 + relu
    qlin_h(sx, i17, half, sw1, sb1, h);
#pragma unroll
    for (int k = 0; k < 8; ++k) {
        h[k].x = fmaxf(h[k].x, 0.f); h[k].y = fmaxf(h[k].y, 0.f);
        h[k].z = fmaxf(h[k].z, 0.f); h[k].w = fmaxf(h[k].w, 0.f);
    }
    __syncthreads();
#pragma unroll
    for (int k = 0; k < 8; ++k) {
        const int co = k >> 1, u = k & 1;
        float* p = sx + co * 2176 + i17 + half * 8 + u * 4;
        p[0] = h[k].x; p[1] = h[k].y; p[2] = h[k].z; p[3] = h[k].w;
    }
    __syncthreads();

    // layer 2
    qlin_h(sx, i17, half, sw2, sb2, h);
    __syncthreads();
#pragma unroll
    for (int k = 0; k < 8; ++k) {
        const int co = k >> 1, u = k & 1;
        float* p = sx + co * 2176 + i17 + half * 8 + u * 4;
        p[0] = h[k].x; p[1] = h[k].y; p[2] = h[k].z; p[3] = h[k].w;
    }
    __syncthreads();

    // coalesced store
#pragma unroll
    for (int c = 0; c < 4; ++c) {
        float* dst = out + (size_t)c * NN * FF + n0 * FF;
        for (int i = tid; i < cnt; i += 256)
            dst[i] = sx[c * 2176 + (i >> 4) * 17 + (i & 15)];
    }
}

// ---------------- launch ----------------
extern "C" void kernel_launch(void* const* d_in, const int* in_sizes, int n_in,
                              void* d_out, int out_size) {
    const float* q    = (const float*)d_in[0];
    const float* ea   = (const float*)d_in[1];
    const int*   ei   = (const int*)d_in[2];
    const float* W1   = (const float*)d_in[3];
    const float* B1   = (const float*)d_in[4];
    const float* W2   = (const float*)d_in[5];
    const float* B2   = (const float*)d_in[6];
    const float* beta = (const float*)d_in[7];
    float* out = (float*)d_out;

    void* degp = nullptr;
    cudaGetSymbolAddress(&degp, g_deg);
    cudaMemsetAsync(degp, 0, NN * sizeof(int));

    k_bucket<<<(EE / 4 + 255) / 256, 256>>>(ei);
    k_node<<<(NN * 32 + 255) / 256, 256>>>(q, ea, beta);
    k_mlp<<<(NN + 127) / 128, 256>>>(W1, B1, W2, B2, out);
}